// round 7
// baseline (speedup 1.0000x reference)
#include <cuda_runtime.h>

#define BATCH   8
#define SEQ     4096
#define DIM     64
#define DS      16
#define CHUNK   64
#define NCHUNK  (SEQ / CHUNK)        // 64
#define ROWS    (BATCH * SEQ)        // 32768

// Scratch (device globals; no allocations allowed)
__device__ float g_A [ROWS * 256];           // per-timestep A_t [row][i*16+l]
__device__ float g_Bx[ROWS * DS];            // per-timestep Bx_t
__device__ float g_P [BATCH * NCHUNK * 256]; // per-chunk cumulative transition
__device__ float g_v [BATCH * NCHUNK * DS];  // per-chunk aggregate input
__device__ float g_h0[BATCH * NCHUNK * DS];  // state entering each chunk
__device__ float g_H [ROWS * DS];            // h_t for every timestep

// ---------------------------------------------------------------------------
// helpers
// ---------------------------------------------------------------------------
__device__ __forceinline__ float f2tf(float f) {
    unsigned u;
    asm("cvt.rna.tf32.f32 %0, %1;" : "=r"(u) : "f"(f));
    return __uint_as_float(u);
}
__device__ __forceinline__ void mma8(float* c,
                                     unsigned a0, unsigned a1, unsigned a2, unsigned a3,
                                     unsigned b0, unsigned b1) {
    asm volatile(
        "mma.sync.aligned.m16n8k8.row.col.f32.tf32.tf32.f32 "
        "{%0,%1,%2,%3},{%4,%5,%6,%7},{%8,%9},{%0,%1,%2,%3};"
        : "+f"(c[0]), "+f"(c[1]), "+f"(c[2]), "+f"(c[3])
        : "r"(a0), "r"(a1), "r"(a2), "r"(a3), "r"(b0), "r"(b1));
}
__device__ __forceinline__ unsigned fu(float f) { return __float_as_uint(f); }

__device__ __forceinline__ void cp16(void* smem_dst, const void* gsrc) {
    unsigned s = (unsigned)__cvta_generic_to_shared(smem_dst);
    asm volatile("cp.async.ca.shared.global [%0], [%1], 16;" :: "r"(s), "l"(gsrc));
}

// frag-major smem indexers (A-operand row-major source, B-operand col-major use)
// A: value (r, k) -> j = (r>>3&1) + 2*(k>>2&1); lane = (r&7)*4 + (k&3)
__device__ __forceinline__ int af_idx(int r, int k) {
    return (((r >> 4) * 8 + (k >> 3)) * 128) + (r & 7) * 16 + (k & 3) * 4
           + ((r >> 3) & 1) + ((k >> 2) & 1) * 2;
}
// B: value (k, n) -> j = (k>>2&1); lane = (n&7)*4 + (k&3)
__device__ __forceinline__ int bf_idx(int k, int n) {
    return (((n >> 3) * 8 + (k >> 3)) * 64) + (n & 7) * 8 + (k & 3) * 2
           + ((k >> 2) & 1);
}

// ---------------------------------------------------------------------------
// Kernel 1a (tensor): A = X @ W_A + b_A   ([32768,64] @ [64,256])
// BM=128, BN=64; frag-major smem, vector frag loads.
// ---------------------------------------------------------------------------
__global__ __launch_bounds__(256) void k_projA(const float* __restrict__ x,
                                               const float* __restrict__ W,
                                               const float* __restrict__ bias) {
    extern __shared__ float sm[];
    float* Xs = sm;             // frag-major, 8 rblk x 8 kblk x 128
    float* Ws = sm + 8192;      // frag-major, 8 nblk x 8 kblk x 64
    const int tid = threadIdx.x;
    const int m0 = blockIdx.x * 128;
    const int n0 = blockIdx.y * 64;

#pragma unroll
    for (int it = 0; it < 8; it++) {           // X tile 128x64
        int i4 = it * 256 + tid;
        int row = i4 >> 4, c4 = (i4 & 15) * 4;
        float4 v = *(const float4*)&x[(long)(m0 + row) * 64 + c4];
        Xs[af_idx(row, c4 + 0)] = f2tf(v.x);
        Xs[af_idx(row, c4 + 1)] = f2tf(v.y);
        Xs[af_idx(row, c4 + 2)] = f2tf(v.z);
        Xs[af_idx(row, c4 + 3)] = f2tf(v.w);
    }
#pragma unroll
    for (int it = 0; it < 4; it++) {           // W tile 64x64
        int i4 = it * 256 + tid;
        int row = i4 >> 4, c4 = (i4 & 15) * 4;
        float4 v = *(const float4*)&W[(long)row * 256 + n0 + c4];
        Ws[bf_idx(row, c4 + 0)] = f2tf(v.x);
        Ws[bf_idx(row, c4 + 1)] = f2tf(v.y);
        Ws[bf_idx(row, c4 + 2)] = f2tf(v.z);
        Ws[bf_idx(row, c4 + 3)] = f2tf(v.w);
    }
    __syncthreads();

    const int wid = tid >> 5, lane = tid & 31;
    const int g = lane >> 2, tig = lane & 3;
    const int wm = wid & 3, wn = wid >> 2;

    float c[2][4][4];
#pragma unroll
    for (int mt = 0; mt < 2; mt++)
#pragma unroll
        for (int nt = 0; nt < 4; nt++)
#pragma unroll
            for (int j = 0; j < 4; j++) c[mt][nt][j] = 0.f;

#pragma unroll
    for (int ks = 0; ks < 8; ks++) {
        float4 a[2];
#pragma unroll
        for (int mt = 0; mt < 2; mt++)
            a[mt] = *(const float4*)&Xs[((wm * 2 + mt) * 8 + ks) * 128 + lane * 4];
        float2 b[4];
#pragma unroll
        for (int nt = 0; nt < 4; nt++)
            b[nt] = *(const float2*)&Ws[((wn * 4 + nt) * 8 + ks) * 64 + lane * 2];
#pragma unroll
        for (int mt = 0; mt < 2; mt++)
#pragma unroll
            for (int nt = 0; nt < 4; nt++)
                mma8(c[mt][nt], fu(a[mt].x), fu(a[mt].y), fu(a[mt].z), fu(a[mt].w),
                     fu(b[nt].x), fu(b[nt].y));
    }

#pragma unroll
    for (int mt = 0; mt < 2; mt++)
#pragma unroll
        for (int nt = 0; nt < 4; nt++) {
            int row = m0 + wm * 32 + mt * 16 + g;
            int col = n0 + wn * 32 + nt * 8 + tig * 2;
            float b0 = bias[col], b1 = bias[col + 1];
            *(float2*)&g_A[(long)row * 256 + col] =
                make_float2(c[mt][nt][0] + b0, c[mt][nt][1] + b1);
            *(float2*)&g_A[(long)(row + 8) * 256 + col] =
                make_float2(c[mt][nt][2] + b0, c[mt][nt][3] + b1);
        }
}

// ---------------------------------------------------------------------------
// Kernel 1b (tensor): Bm = X @ W_B + b_B fused with Bx = Bm . x
// BM=128, BN=128; frag-major smem.
// ---------------------------------------------------------------------------
__global__ __launch_bounds__(256) void k_projB(const float* __restrict__ x,
                                               const float* __restrict__ W,
                                               const float* __restrict__ bias) {
    extern __shared__ float sm[];
    float* Xs  = sm;             // frag-major 8 rblk x 8 kblk x 128 = 8192
    float* Ws  = sm + 8192;      // frag-major 16 nblk x 8 kblk x 64 = 8192
    float* red = sm + 16384;     // [128][4]
    const int tid = threadIdx.x;
    const int m0 = blockIdx.x * 128;
    const int n0 = blockIdx.y * 128;

#pragma unroll
    for (int it = 0; it < 8; it++) {
        int i4 = it * 256 + tid;
        int row = i4 >> 4, c4 = (i4 & 15) * 4;
        float4 v = *(const float4*)&x[(long)(m0 + row) * 64 + c4];
        Xs[af_idx(row, c4 + 0)] = f2tf(v.x);
        Xs[af_idx(row, c4 + 1)] = f2tf(v.y);
        Xs[af_idx(row, c4 + 2)] = f2tf(v.z);
        Xs[af_idx(row, c4 + 3)] = f2tf(v.w);
    }
#pragma unroll
    for (int it = 0; it < 8; it++) {           // W tile 64x128
        int i4 = it * 256 + tid;
        int row = i4 >> 5, c4 = (i4 & 31) * 4;
        float4 v = *(const float4*)&W[(long)row * 1024 + n0 + c4];
        Ws[bf_idx(row, c4 + 0)] = f2tf(v.x);
        Ws[bf_idx(row, c4 + 1)] = f2tf(v.y);
        Ws[bf_idx(row, c4 + 2)] = f2tf(v.z);
        Ws[bf_idx(row, c4 + 3)] = f2tf(v.w);
    }
    __syncthreads();

    const int wid = tid >> 5, lane = tid & 31;
    const int g = lane >> 2, tig = lane & 3;
    const int wm = wid & 1, wn = wid >> 1;    // 2 M-warps x 4 N-warps
    const int mbase = wm * 64, nbase = wn * 32;

    float c[4][4][4];
#pragma unroll
    for (int mt = 0; mt < 4; mt++)
#pragma unroll
        for (int nt = 0; nt < 4; nt++)
#pragma unroll
            for (int j = 0; j < 4; j++) c[mt][nt][j] = 0.f;

#pragma unroll
    for (int ks = 0; ks < 8; ks++) {
        float4 a[4];
#pragma unroll
        for (int mt = 0; mt < 4; mt++)
            a[mt] = *(const float4*)&Xs[((wm * 4 + mt) * 8 + ks) * 128 + lane * 4];
        float2 b[4];
#pragma unroll
        for (int nt = 0; nt < 4; nt++)
            b[nt] = *(const float2*)&Ws[((wn * 4 + nt) * 8 + ks) * 64 + lane * 2];
#pragma unroll
        for (int mt = 0; mt < 4; mt++)
#pragma unroll
            for (int nt = 0; nt < 4; nt++)
                mma8(c[mt][nt], fu(a[mt].x), fu(a[mt].y), fu(a[mt].z), fu(a[mt].w),
                     fu(b[nt].x), fu(b[nt].y));
    }

    // epilogue: Bx partials (x read back from frag-major Xs)
    float bv0[4], bv1[4];
    int dl[4];
#pragma unroll
    for (int nt = 0; nt < 4; nt++) {
        int d0 = nbase + nt * 8 + tig * 2;
        dl[nt] = d0 & 63;
        bv0[nt] = bias[n0 + d0];
        bv1[nt] = bias[n0 + d0 + 1];
    }
#pragma unroll
    for (int mt = 0; mt < 4; mt++) {
        int r0 = mbase + mt * 16 + g;
        int r1 = r0 + 8;
        float p0 = 0.f, p1 = 0.f;
#pragma unroll
        for (int nt = 0; nt < 4; nt++) {
            float x00 = Xs[af_idx(r0, dl[nt])];
            float x01 = Xs[af_idx(r0, dl[nt] + 1)];
            float x10 = Xs[af_idx(r1, dl[nt])];
            float x11 = Xs[af_idx(r1, dl[nt] + 1)];
            p0 += (c[mt][nt][0] + bv0[nt]) * x00 + (c[mt][nt][1] + bv1[nt]) * x01;
            p1 += (c[mt][nt][2] + bv0[nt]) * x10 + (c[mt][nt][3] + bv1[nt]) * x11;
        }
        p0 += __shfl_xor_sync(0xffffffffu, p0, 1, 4);
        p0 += __shfl_xor_sync(0xffffffffu, p0, 2, 4);
        p1 += __shfl_xor_sync(0xffffffffu, p1, 1, 4);
        p1 += __shfl_xor_sync(0xffffffffu, p1, 2, 4);
        if (tig == 0) {
            red[r0 * 4 + wn] = p0;
            red[r1 * 4 + wn] = p1;
        }
    }
    __syncthreads();
    {
        int r = tid >> 1, grp = tid & 1;
        float bx = red[r * 4 + grp * 2] + red[r * 4 + grp * 2 + 1];
        int n_idx = blockIdx.y * 2 + grp;
        g_Bx[(long)(m0 + r) * DS + n_idx] = bx;
    }
}

// ---------------------------------------------------------------------------
// Kernel 1c: per-chunk P,v via binary tree combine (6 levels)
// ---------------------------------------------------------------------------
#define MSTRIDE 272
#define CK_BUFA 0
#define CK_BUFB (32 * MSTRIDE)
#define CK_VX   (2 * 32 * MSTRIDE)
#define CK_VA   (CK_VX + 64 * 16)
#define CK_VB   (CK_VA + 32 * 16)
#define CK_SMEM (CK_VB + 32 * 16)

__global__ __launch_bounds__(256) void k_chunk() {
    extern __shared__ float sm[];
    float* bufA = sm + CK_BUFA;
    float* bufB = sm + CK_BUFB;
    float* VX   = sm + CK_VX;
    float* Va   = sm + CK_VA;
    float* Vb   = sm + CK_VB;
    const int tid = threadIdx.x;
    const int bc = blockIdx.x;
    const long rowbase = (long)bc * CHUNK;

#pragma unroll
    for (int it = 0; it < 8; it++) {
        int i4 = it * 256 + tid;
        int m = i4 >> 6, e4 = (i4 & 63) * 4;
        *(float4*)&bufA[m * MSTRIDE + e4] =
            *(const float4*)&g_A[(rowbase + 2 * m) * 256 + e4];
    }
    *(float4*)&VX[tid * 4] = *(const float4*)&g_Bx[rowbase * DS + tid * 4];
    __syncthreads();

#pragma unroll
    for (int rep = 0; rep < 2; rep++) {
        int r = rep * 256 + tid;
        int m = r >> 4, i = r & 15;
        const float* arow = &g_A[(rowbase + 2 * m + 1) * 256 + i * 16];
        float4 a0 = *(const float4*)&arow[0];
        float4 a1 = *(const float4*)&arow[4];
        float4 a2 = *(const float4*)&arow[8];
        float4 a3 = *(const float4*)&arow[12];
        float av[16] = {a0.x, a0.y, a0.z, a0.w, a1.x, a1.y, a1.z, a1.w,
                        a2.x, a2.y, a2.z, a2.w, a3.x, a3.y, a3.z, a3.w};
        float acc[16];
#pragma unroll
        for (int l = 0; l < 16; l++) acc[l] = 0.f;
        float accv = VX[(2 * m + 1) * 16 + i];
#pragma unroll
        for (int q = 0; q < 16; q++) {
            float aq = av[q];
            float4 b0 = *(const float4*)&bufA[m * MSTRIDE + q * 16 + 0];
            float4 b1 = *(const float4*)&bufA[m * MSTRIDE + q * 16 + 4];
            float4 b2 = *(const float4*)&bufA[m * MSTRIDE + q * 16 + 8];
            float4 b3 = *(const float4*)&bufA[m * MSTRIDE + q * 16 + 12];
            acc[0]  += aq * b0.x; acc[1]  += aq * b0.y;
            acc[2]  += aq * b0.z; acc[3]  += aq * b0.w;
            acc[4]  += aq * b1.x; acc[5]  += aq * b1.y;
            acc[6]  += aq * b1.z; acc[7]  += aq * b1.w;
            acc[8]  += aq * b2.x; acc[9]  += aq * b2.y;
            acc[10] += aq * b2.z; acc[11] += aq * b2.w;
            acc[12] += aq * b3.x; acc[13] += aq * b3.y;
            acc[14] += aq * b3.z; acc[15] += aq * b3.w;
            accv += aq * VX[2 * m * 16 + q];
        }
#pragma unroll
        for (int l4 = 0; l4 < 4; l4++)
            *(float4*)&bufB[m * MSTRIDE + i * 16 + l4 * 4] =
                make_float4(acc[l4 * 4], acc[l4 * 4 + 1],
                            acc[l4 * 4 + 2], acc[l4 * 4 + 3]);
        Vb[m * 16 + i] = accv;
    }
    __syncthreads();

    float* src = bufB; float* dst = bufA;
    float* vs = Vb;    float* vd = Va;
#pragma unroll
    for (int lev = 1; lev <= 5; lev++) {
        int nmerge = 32 >> lev;
        int rows = nmerge * 16;
        if (tid < rows) {
            int m = tid >> 4, i = tid & 15;
            const float* a1p = &src[(2 * m + 1) * MSTRIDE + i * 16];
            float4 a0 = *(const float4*)&a1p[0];
            float4 a1 = *(const float4*)&a1p[4];
            float4 a2 = *(const float4*)&a1p[8];
            float4 a3 = *(const float4*)&a1p[12];
            float av[16] = {a0.x, a0.y, a0.z, a0.w, a1.x, a1.y, a1.z, a1.w,
                            a2.x, a2.y, a2.z, a2.w, a3.x, a3.y, a3.z, a3.w};
            float acc[16];
#pragma unroll
            for (int l = 0; l < 16; l++) acc[l] = 0.f;
            float accv = vs[(2 * m + 1) * 16 + i];
#pragma unroll
            for (int q = 0; q < 16; q++) {
                float aq = av[q];
                const float* bp = &src[2 * m * MSTRIDE + q * 16];
                float4 b0 = *(const float4*)&bp[0];
                float4 b1 = *(const float4*)&bp[4];
                float4 b2 = *(const float4*)&bp[8];
                float4 b3 = *(const float4*)&bp[12];
                acc[0]  += aq * b0.x; acc[1]  += aq * b0.y;
                acc[2]  += aq * b0.z; acc[3]  += aq * b0.w;
                acc[4]  += aq * b1.x; acc[5]  += aq * b1.y;
                acc[6]  += aq * b1.z; acc[7]  += aq * b1.w;
                acc[8]  += aq * b2.x; acc[9]  += aq * b2.y;
                acc[10] += aq * b2.z; acc[11] += aq * b2.w;
                acc[12] += aq * b3.x; acc[13] += aq * b3.y;
                acc[14] += aq * b3.z; acc[15] += aq * b3.w;
                accv += aq * vs[2 * m * 16 + q];
            }
#pragma unroll
            for (int l4 = 0; l4 < 4; l4++)
                *(float4*)&dst[m * MSTRIDE + i * 16 + l4 * 4] =
                    make_float4(acc[l4 * 4], acc[l4 * 4 + 1],
                                acc[l4 * 4 + 2], acc[l4 * 4 + 3]);
            vd[m * 16 + i] = accv;
        }
        __syncthreads();
        float* t = src; src = dst; dst = t;
        float* tv = vs; vs = vd; vd = tv;
    }

    g_P[(long)bc * 256 + tid] = src[tid];
    if (tid < 16) g_v[bc * DS + tid] = vs[tid];
}

// ---------------------------------------------------------------------------
// Kernel 2: inter-chunk scan. One block per batch; cp.async ring, depth 8.
// ---------------------------------------------------------------------------
#define RING_ROW 20
#define RING_STAGE (16 * RING_ROW + 16)
#define RING_DEPTH 8

__global__ __launch_bounds__(32) void k_scan() {
    __shared__ float ring[RING_DEPTH][RING_STAGE];
    const int b = blockIdx.x;
    const int lane = threadIdx.x;
    const long base = (long)b * NCHUNK;

#pragma unroll
    for (int c = 0; c < RING_DEPTH; c++) {
        int slot = c & (RING_DEPTH - 1);
        if (lane < 16) {
            const float* src = &g_P[(base + c) * 256 + lane * 16];
#pragma unroll
            for (int j = 0; j < 4; j++)
                cp16(&ring[slot][lane * RING_ROW + j * 4], src + j * 4);
        }
        if (lane < 4)
            cp16(&ring[slot][16 * RING_ROW + lane * 4],
                 &g_v[(base + c) * DS + lane * 4]);
        asm volatile("cp.async.commit_group;");
    }

    float h[16];
#pragma unroll
    for (int q = 0; q < 16; q++) h[q] = 0.f;
    float mine = 0.f;

    for (int c = 0; c < NCHUNK; c++) {
        asm volatile("cp.async.wait_group %0;" :: "n"(RING_DEPTH - 1));
        __syncwarp();
        float hn = 0.f;
        if (lane < 16) {
            g_h0[(base + c) * DS + lane] = mine;
            const float* R = &ring[c & (RING_DEPTH - 1)][lane * RING_ROW];
            float4 p0 = *(const float4*)&R[0];
            float4 p1 = *(const float4*)&R[4];
            float4 p2 = *(const float4*)&R[8];
            float4 p3 = *(const float4*)&R[12];
            float v = ring[c & (RING_DEPTH - 1)][16 * RING_ROW + lane];
            float s0 = v + p0.x * h[0] + p0.y * h[1] + p0.z * h[2] + p0.w * h[3];
            float s1 = p1.x * h[4] + p1.y * h[5] + p1.z * h[6] + p1.w * h[7];
            float s2 = p2.x * h[8] + p2.y * h[9] + p2.z * h[10] + p2.w * h[11];
            float s3 = p3.x * h[12] + p3.y * h[13] + p3.z * h[14] + p3.w * h[15];
            hn = (s0 + s1) + (s2 + s3);
            mine = hn;
        }
#pragma unroll
        for (int q = 0; q < 16; q++)
            h[q] = __shfl_sync(0xffffffffu, hn, q);
        if (c + RING_DEPTH < NCHUNK) {
            int slot = c & (RING_DEPTH - 1);
            if (lane < 16) {
                const float* src = &g_P[(base + c + RING_DEPTH) * 256 + lane * 16];
#pragma unroll
                for (int j = 0; j < 4; j++)
                    cp16(&ring[slot][lane * RING_ROW + j * 4], src + j * 4);
            }
            if (lane < 4)
                cp16(&ring[slot][16 * RING_ROW + lane * 4],
                     &g_v[(base + c + RING_DEPTH) * DS + lane * 4]);
        }
        asm volatile("cp.async.commit_group;");
    }
}

// ---------------------------------------------------------------------------
// Kernel 2b: per-chunk replay -> g_H
// ---------------------------------------------------------------------------
__global__ __launch_bounds__(32) void k_replay() {
    const int bc = blockIdx.x;
    const int lane = threadIdx.x;
    const long rowbase = (long)bc * CHUNK;

    float h[16];
#pragma unroll
    for (int q = 0; q < 16; q++) h[q] = g_h0[bc * DS + q];

    float4 a0 = {0,0,0,0}, a1 = a0, a2 = a0, a3 = a0;
    float bx = 0.f;
    if (lane < 16) {
        const float* Arow = &g_A[rowbase * 256 + lane * 16];
        a0 = *(const float4*)&Arow[0];
        a1 = *(const float4*)&Arow[4];
        a2 = *(const float4*)&Arow[8];
        a3 = *(const float4*)&Arow[12];
        bx = g_Bx[rowbase * DS + lane];
    }
    for (int t = 0; t < CHUNK; t++) {
        float4 n0 = a0, n1 = a1, n2 = a2, n3 = a3;
        float bxn = bx;
        if (lane < 16 && t + 1 < CHUNK) {
            const float* An = &g_A[(rowbase + t + 1) * 256 + lane * 16];
            n0 = *(const float4*)&An[0];
            n1 = *(const float4*)&An[4];
            n2 = *(const float4*)&An[8];
            n3 = *(const float4*)&An[12];
            bxn = g_Bx[(rowbase + t + 1) * DS + lane];
        }
        float hn = 0.f;
        if (lane < 16) {
            float s0 = bx + a0.x * h[0] + a0.y * h[1] + a0.z * h[2] + a0.w * h[3];
            float s1 = a1.x * h[4] + a1.y * h[5] + a1.z * h[6] + a1.w * h[7];
            float s2 = a2.x * h[8] + a2.y * h[9] + a2.z * h[10] + a2.w * h[11];
            float s3 = a3.x * h[12] + a3.y * h[13] + a3.z * h[14] + a3.w * h[15];
            hn = (s0 + s1) + (s2 + s3);
            g_H[(rowbase + t) * DS + lane] = hn;
        }
#pragma unroll
        for (int q = 0; q < 16; q++)
            h[q] = __shfl_sync(0xffffffffu, hn, q);
        a0 = n0; a1 = n1; a2 = n2; a3 = n3; bx = bxn;
    }
}

// ---------------------------------------------------------------------------
// Kernel 3 (tensor): out[m,d] = sum_n h[m,n] * (x @ W_C[:,n,:])[m,d] + h @ b_C'
// BM=128; frag-major smem; W reg-pipelined per n.
// ---------------------------------------------------------------------------
#define KC_WS   8192                    // Xs frag-major
#define KC_HS   (KC_WS + 4096)          // Ws frag-major per-n
#define KC_BS   (KC_HS + 128 * 17)      // Hs row-major
#define KC_SMEM (KC_BS + 16 * 68)       // b_C row-major

__global__ __launch_bounds__(256) void k_outC(const float* __restrict__ x,
                                              const float* __restrict__ W_C,
                                              const float* __restrict__ b_C,
                                              float* __restrict__ out) {
    extern __shared__ float sm[];
    float* Xs = sm;             // frag-major 8 rblk x 8 kblk x 128
    float* Ws = sm + KC_WS;     // frag-major 8 nblk x 8 kblk x 64
    float* Hs = sm + KC_HS;     // [128][17] fp32 h
    float* Bs = sm + KC_BS;     // [16][68] b_C
    const int tid = threadIdx.x;
    const int m0 = blockIdx.x * 128;

#pragma unroll
    for (int it = 0; it < 8; it++) {
        int i4 = it * 256 + tid;
        int row = i4 >> 4, c4 = (i4 & 15) * 4;
        float4 v = *(const float4*)&x[(long)(m0 + row) * 64 + c4];
        Xs[af_idx(row, c4 + 0)] = f2tf(v.x);
        Xs[af_idx(row, c4 + 1)] = f2tf(v.y);
        Xs[af_idx(row, c4 + 2)] = f2tf(v.z);
        Xs[af_idx(row, c4 + 3)] = f2tf(v.w);
    }
#pragma unroll
    for (int it = 0; it < 2; it++) {
        int i4 = it * 256 + tid;
        int row = i4 >> 2, c4 = (i4 & 3) * 4;
        float4 v = *(const float4*)&g_H[(long)(m0 + row) * DS + c4];
        Hs[row * 17 + c4 + 0] = v.x;
        Hs[row * 17 + c4 + 1] = v.y;
        Hs[row * 17 + c4 + 2] = v.z;
        Hs[row * 17 + c4 + 3] = v.w;
    }

    int wk[4], wd[4];
#pragma unroll
    for (int it = 0; it < 4; it++) {
        int i4 = it * 256 + tid;
        wk[it] = i4 >> 4;
        wd[it] = (i4 & 15) * 4;
    }
    float4 wreg[4];
#pragma unroll
    for (int it = 0; it < 4; it++)
        wreg[it] = *(const float4*)&W_C[(long)wk[it] * 1024 + wd[it]];   // n=0

    const int wid = tid >> 5, lane = tid & 31;
    const int g = lane >> 2, tig = lane & 3;
    const int wm = wid & 3, wn = wid >> 2;
    const int mbase = wm * 32, nbase = wn * 32;

    float oacc[2][4][4];
#pragma unroll
    for (int mt = 0; mt < 2; mt++)
#pragma unroll
        for (int nt = 0; nt < 4; nt++)
#pragma unroll
            for (int j = 0; j < 4; j++) oacc[mt][nt][j] = 0.f;

    for (int n = 0; n < 16; n++) {
        __syncthreads();
#pragma unroll
        for (int it = 0; it < 4; it++) {
            Ws[bf_idx(wk[it], wd[it] + 0)] = f2tf(wreg[it].x);
            Ws[bf_idx(wk[it], wd[it] + 1)] = f2tf(wreg[it].y);
            Ws[bf_idx(wk[it], wd[it] + 2)] = f2tf(wreg[it].z);
            Ws[bf_idx(wk[it], wd[it] + 3)] = f2tf(wreg[it].w);
        }
        __syncthreads();
        if (n + 1 < 16) {
#pragma unroll
            for (int it = 0; it < 4; it++)
                wreg[it] = *(const float4*)
                    &W_C[(long)wk[it] * 1024 + (n + 1) * 64 + wd[it]];
        }

        float c[2][4][4];
#pragma unroll
        for (int mt = 0; mt < 2; mt++)
#pragma unroll
            for (int nt = 0; nt < 4; nt++)
#pragma unroll
                for (int j = 0; j < 4; j++) c[mt][nt][j] = 0.f;

#pragma unroll
        for (int ks = 0; ks < 8; ks++) {
            float4 a[2];
#pragma unroll
            for (int mt = 0; mt < 2; mt++)
                a[mt] = *(const float4*)&Xs[((wm * 2 + mt) * 8 + ks) * 128 + lane * 4];
            float2 b[4];
#pragma unroll
            for (int nt = 0; nt < 4; nt++)
                b[nt] = *(const float2*)&Ws[((wn * 4 + nt) * 8 + ks) * 64 + lane * 2];
#pragma unroll
            for (int mt = 0; mt < 2; mt++)
#pragma unroll
                for (int nt = 0; nt < 4; nt++)
                    mma8(c[mt][nt], fu(a[mt].x), fu(a[mt].y), fu(a[mt].z), fu(a[mt].w),
                         fu(b[nt].x), fu(b[nt].y));
        }

#pragma unroll
        for (int mt = 0; mt < 2; mt++) {
            int r0 = mbase + mt * 16 + g;
            float ha = Hs[r0 * 17 + n];
            float hb = Hs[(r0 + 8) * 17 + n];
#pragma unroll
            for (int nt = 0; nt < 4; nt++) {
                oacc[mt][nt][0] += ha * c[mt][nt][0];
                oacc[mt][nt][1] += ha * c[mt][nt][1];
                oacc[mt][nt][2] += hb * c[mt][nt][2];
                oacc[mt][nt][3] += hb * c[mt][nt][3];
            }
        }
    }

    // bias
    {
        int nn = tid >> 4, c4 = (tid & 15) * 4;
        float4 v = *(const float4*)&b_C[nn * 64 + c4];
        Bs[nn * 68 + c4 + 0] = v.x;
        Bs[nn * 68 + c4 + 1] = v.y;
        Bs[nn * 68 + c4 + 2] = v.z;
        Bs[nn * 68 + c4 + 3] = v.w;
    }
    __syncthreads();

#pragma unroll
    for (int mt = 0; mt < 2; mt++) {
        int r0 = mbase + mt * 16 + g;
        int r1 = r0 + 8;
#pragma unroll
        for (int nt = 0; nt < 4; nt++) {
            int col = nbase + nt * 8 + tig * 2;
            float s00 = 0.f, s01 = 0.f, s10 = 0.f, s11 = 0.f;
#pragma unroll
            for (int nn = 0; nn < 16; nn++) {
                float ha = Hs[r0 * 17 + nn], hb = Hs[r1 * 17 + nn];
                float w0 = Bs[nn * 68 + col], w1 = Bs[nn * 68 + col + 1];
                s00 += ha * w0; s01 += ha * w1;
                s10 += hb * w0; s11 += hb * w1;
            }
            *(float2*)&out[(long)(m0 + r0) * 64 + col] =
                make_float2(oacc[mt][nt][0] + s00, oacc[mt][nt][1] + s01);
            *(float2*)&out[(long)(m0 + r1) * 64 + col] =
                make_float2(oacc[mt][nt][2] + s10, oacc[mt][nt][3] + s11);
        }
    }
}

// ---------------------------------------------------------------------------
extern "C" void kernel_launch(void* const* d_in, const int* in_sizes, int n_in,
                              void* d_out, int out_size) {
    const float* x   = (const float*)d_in[0];
    const float* W_A = (const float*)d_in[1];
    const float* b_A = (const float*)d_in[2];
    const float* W_B = (const float*)d_in[3];
    const float* b_B = (const float*)d_in[4];
    const float* W_C = (const float*)d_in[5];
    const float* b_C = (const float*)d_in[6];
    float* out = (float*)d_out;

    const int smA = (8192 + 4096) * sizeof(float);
    const int smB = (8192 + 8192 + 512) * sizeof(float);
    const int smC = CK_SMEM * sizeof(float);
    const int smO = KC_SMEM * sizeof(float);
    cudaFuncSetAttribute(k_projA, cudaFuncAttributeMaxDynamicSharedMemorySize, smA);
    cudaFuncSetAttribute(k_projB, cudaFuncAttributeMaxDynamicSharedMemorySize, smB);
    cudaFuncSetAttribute(k_chunk, cudaFuncAttributeMaxDynamicSharedMemorySize, smC);
    cudaFuncSetAttribute(k_outC,  cudaFuncAttributeMaxDynamicSharedMemorySize, smO);

    k_projA<<<dim3(ROWS / 128, 4), 256, smA>>>(x, W_A, b_A);
    k_projB<<<dim3(ROWS / 128, 8), 256, smB>>>(x, W_B, b_B);
    k_chunk<<<BATCH * NCHUNK, 256, smC>>>();
    k_scan<<<BATCH, 32>>>();
    k_replay<<<BATCH * NCHUNK, 32>>>();
    k_outC<<<ROWS / 128, 256, smO>>>(x, W_C, b_C, out);
}

// round 8
// speedup vs baseline: 1.7169x; 1.7169x over previous
#include <cuda_runtime.h>

#define BATCH   8
#define SEQ     4096
#define DIM     64
#define DS      16
#define CHUNK   64
#define NCHUNK  (SEQ / CHUNK)        // 64
#define ROWS    (BATCH * SEQ)        // 32768
#define NSUPER  8                    // superchunks per batch
#define SCH     (NCHUNK / NSUPER)    // 8 chunks per superchunk

// Scratch (device globals; no allocations allowed)
__device__ float g_A  [ROWS * 256];            // per-timestep A_t [row][i*16+l]
__device__ float g_Bx [ROWS * DS];             // per-timestep Bx_t
__device__ float g_P  [BATCH * NCHUNK * 256];  // per-chunk cumulative transition
__device__ float g_v  [BATCH * NCHUNK * DS];   // per-chunk aggregate input
__device__ float g_h0 [BATCH * NCHUNK * DS];   // state entering each chunk
__device__ float g_H  [ROWS * DS];             // h_t for every timestep
__device__ float g_SP [BATCH * NSUPER * 256];  // per-superchunk transition
__device__ float g_Sv [BATCH * NSUPER * DS];   // per-superchunk aggregate
__device__ float g_sh0[BATCH * NSUPER * DS];   // state entering each superchunk

// ---------------------------------------------------------------------------
// helpers: tf32 convert + m16n8k8 tf32 mma
// ---------------------------------------------------------------------------
__device__ __forceinline__ float f2tf(float f) {
    unsigned u;
    asm("cvt.rna.tf32.f32 %0, %1;" : "=r"(u) : "f"(f));
    return __uint_as_float(u);
}
__device__ __forceinline__ void mma8(float* c,
                                     unsigned a0, unsigned a1, unsigned a2, unsigned a3,
                                     unsigned b0, unsigned b1) {
    asm volatile(
        "mma.sync.aligned.m16n8k8.row.col.f32.tf32.tf32.f32 "
        "{%0,%1,%2,%3},{%4,%5,%6,%7},{%8,%9},{%0,%1,%2,%3};"
        : "+f"(c[0]), "+f"(c[1]), "+f"(c[2]), "+f"(c[3])
        : "r"(a0), "r"(a1), "r"(a2), "r"(a3), "r"(b0), "r"(b1));
}
__device__ __forceinline__ unsigned fu(float f) { return __float_as_uint(f); }

// ---------------------------------------------------------------------------
// Kernel 1a (tensor): A = X @ W_A + b_A   ([32768,64] @ [64,256])
// ---------------------------------------------------------------------------
__global__ __launch_bounds__(256) void k_projA(const float* __restrict__ x,
                                               const float* __restrict__ W,
                                               const float* __restrict__ bias) {
    extern __shared__ float sm[];
    float* Xs = sm;             // [128][68]
    float* Ws = sm + 128 * 68;  // [64][68]
    const int tid = threadIdx.x;
    const int m0 = blockIdx.x * 128;
    const int n0 = blockIdx.y * 64;

#pragma unroll
    for (int it = 0; it < 8; it++) {
        int i4 = it * 256 + tid;
        int row = i4 >> 4, c4 = (i4 & 15) * 4;
        float4 v = *(const float4*)&x[(long)(m0 + row) * 64 + c4];
        Xs[row * 68 + c4 + 0] = f2tf(v.x);
        Xs[row * 68 + c4 + 1] = f2tf(v.y);
        Xs[row * 68 + c4 + 2] = f2tf(v.z);
        Xs[row * 68 + c4 + 3] = f2tf(v.w);
    }
#pragma unroll
    for (int it = 0; it < 4; it++) {
        int i4 = it * 256 + tid;
        int row = i4 >> 4, c4 = (i4 & 15) * 4;
        float4 v = *(const float4*)&W[(long)row * 256 + n0 + c4];
        Ws[row * 68 + c4 + 0] = f2tf(v.x);
        Ws[row * 68 + c4 + 1] = f2tf(v.y);
        Ws[row * 68 + c4 + 2] = f2tf(v.z);
        Ws[row * 68 + c4 + 3] = f2tf(v.w);
    }
    __syncthreads();

    const int wid = tid >> 5, lane = tid & 31;
    const int g = lane >> 2, tig = lane & 3;
    const int wm = wid & 3, wn = wid >> 2;
    const int mbase = wm * 32, nbase = wn * 32;

    float c[2][4][4];
#pragma unroll
    for (int mt = 0; mt < 2; mt++)
#pragma unroll
        for (int nt = 0; nt < 4; nt++)
#pragma unroll
            for (int j = 0; j < 4; j++) c[mt][nt][j] = 0.f;

#pragma unroll
    for (int ks = 0; ks < 8; ks++) {
        const int k0 = ks * 8;
        unsigned a[2][4];
#pragma unroll
        for (int mt = 0; mt < 2; mt++) {
            int r = mbase + mt * 16 + g;
            a[mt][0] = fu(Xs[r * 68 + k0 + tig]);
            a[mt][1] = fu(Xs[(r + 8) * 68 + k0 + tig]);
            a[mt][2] = fu(Xs[r * 68 + k0 + tig + 4]);
            a[mt][3] = fu(Xs[(r + 8) * 68 + k0 + tig + 4]);
        }
        unsigned b[4][2];
#pragma unroll
        for (int nt = 0; nt < 4; nt++) {
            int n = nbase + nt * 8 + g;
            b[nt][0] = fu(Ws[(k0 + tig) * 68 + n]);
            b[nt][1] = fu(Ws[(k0 + tig + 4) * 68 + n]);
        }
#pragma unroll
        for (int mt = 0; mt < 2; mt++)
#pragma unroll
            for (int nt = 0; nt < 4; nt++)
                mma8(c[mt][nt], a[mt][0], a[mt][1], a[mt][2], a[mt][3],
                     b[nt][0], b[nt][1]);
    }

#pragma unroll
    for (int mt = 0; mt < 2; mt++)
#pragma unroll
        for (int nt = 0; nt < 4; nt++) {
            int row = m0 + mbase + mt * 16 + g;
            int col = n0 + nbase + nt * 8 + tig * 2;
            float b0 = bias[col], b1 = bias[col + 1];
            *(float2*)&g_A[(long)row * 256 + col] =
                make_float2(c[mt][nt][0] + b0, c[mt][nt][1] + b1);
            *(float2*)&g_A[(long)(row + 8) * 256 + col] =
                make_float2(c[mt][nt][2] + b0, c[mt][nt][3] + b1);
        }
}

// ---------------------------------------------------------------------------
// Kernel 1b (tensor): Bm = X @ W_B + b_B fused with Bx = Bm . x
// ---------------------------------------------------------------------------
__global__ __launch_bounds__(256) void k_projB(const float* __restrict__ x,
                                               const float* __restrict__ W,
                                               const float* __restrict__ bias) {
    extern __shared__ float sm[];
    float* Xs  = sm;                        // [128][68]
    float* Ws  = sm + 128 * 68;             // [64][132]
    float* red = Ws + 64 * 132;             // [128][4]
    const int tid = threadIdx.x;
    const int m0 = blockIdx.x * 128;
    const int n0 = blockIdx.y * 128;

#pragma unroll
    for (int it = 0; it < 8; it++) {
        int i4 = it * 256 + tid;
        int row = i4 >> 4, c4 = (i4 & 15) * 4;
        float4 v = *(const float4*)&x[(long)(m0 + row) * 64 + c4];
        Xs[row * 68 + c4 + 0] = f2tf(v.x);
        Xs[row * 68 + c4 + 1] = f2tf(v.y);
        Xs[row * 68 + c4 + 2] = f2tf(v.z);
        Xs[row * 68 + c4 + 3] = f2tf(v.w);
    }
#pragma unroll
    for (int it = 0; it < 8; it++) {
        int i4 = it * 256 + tid;
        int row = i4 >> 5, c4 = (i4 & 31) * 4;
        float4 v = *(const float4*)&W[(long)row * 1024 + n0 + c4];
        Ws[row * 132 + c4 + 0] = f2tf(v.x);
        Ws[row * 132 + c4 + 1] = f2tf(v.y);
        Ws[row * 132 + c4 + 2] = f2tf(v.z);
        Ws[row * 132 + c4 + 3] = f2tf(v.w);
    }
    __syncthreads();

    const int wid = tid >> 5, lane = tid & 31;
    const int g = lane >> 2, tig = lane & 3;
    const int wm = wid & 1, wn = wid >> 1;
    const int mbase = wm * 64, nbase = wn * 32;

    float c[4][4][4];
#pragma unroll
    for (int mt = 0; mt < 4; mt++)
#pragma unroll
        for (int nt = 0; nt < 4; nt++)
#pragma unroll
            for (int j = 0; j < 4; j++) c[mt][nt][j] = 0.f;

#pragma unroll
    for (int ks = 0; ks < 8; ks++) {
        const int k0 = ks * 8;
        unsigned a[4][4];
#pragma unroll
        for (int mt = 0; mt < 4; mt++) {
            int r = mbase + mt * 16 + g;
            a[mt][0] = fu(Xs[r * 68 + k0 + tig]);
            a[mt][1] = fu(Xs[(r + 8) * 68 + k0 + tig]);
            a[mt][2] = fu(Xs[r * 68 + k0 + tig + 4]);
            a[mt][3] = fu(Xs[(r + 8) * 68 + k0 + tig + 4]);
        }
        unsigned b[4][2];
#pragma unroll
        for (int nt = 0; nt < 4; nt++) {
            int n = nbase + nt * 8 + g;
            b[nt][0] = fu(Ws[(k0 + tig) * 132 + n]);
            b[nt][1] = fu(Ws[(k0 + tig + 4) * 132 + n]);
        }
#pragma unroll
        for (int mt = 0; mt < 4; mt++)
#pragma unroll
            for (int nt = 0; nt < 4; nt++)
                mma8(c[mt][nt], a[mt][0], a[mt][1], a[mt][2], a[mt][3],
                     b[nt][0], b[nt][1]);
    }

    float bv0[4], bv1[4];
    int dl[4];
#pragma unroll
    for (int nt = 0; nt < 4; nt++) {
        int d0 = nbase + nt * 8 + tig * 2;
        dl[nt] = d0 & 63;
        bv0[nt] = bias[n0 + d0];
        bv1[nt] = bias[n0 + d0 + 1];
    }
#pragma unroll
    for (int mt = 0; mt < 4; mt++) {
        int r0 = mbase + mt * 16 + g;
        int r1 = r0 + 8;
        float p0 = 0.f, p1 = 0.f;
#pragma unroll
        for (int nt = 0; nt < 4; nt++) {
            float x00 = Xs[r0 * 68 + dl[nt]];
            float x01 = Xs[r0 * 68 + dl[nt] + 1];
            float x10 = Xs[r1 * 68 + dl[nt]];
            float x11 = Xs[r1 * 68 + dl[nt] + 1];
            p0 += (c[mt][nt][0] + bv0[nt]) * x00 + (c[mt][nt][1] + bv1[nt]) * x01;
            p1 += (c[mt][nt][2] + bv0[nt]) * x10 + (c[mt][nt][3] + bv1[nt]) * x11;
        }
        p0 += __shfl_xor_sync(0xffffffffu, p0, 1, 4);
        p0 += __shfl_xor_sync(0xffffffffu, p0, 2, 4);
        p1 += __shfl_xor_sync(0xffffffffu, p1, 1, 4);
        p1 += __shfl_xor_sync(0xffffffffu, p1, 2, 4);
        if (tig == 0) {
            red[r0 * 4 + wn] = p0;
            red[r1 * 4 + wn] = p1;
        }
    }
    __syncthreads();
    {
        int r = tid >> 1, grp = tid & 1;
        float bx = red[r * 4 + grp * 2] + red[r * 4 + grp * 2 + 1];
        int n_idx = blockIdx.y * 2 + grp;
        g_Bx[(long)(m0 + r) * DS + n_idx] = bx;
    }
}

// ---------------------------------------------------------------------------
// Kernel 1c: per-chunk P,v via binary tree combine (6 levels)
// ---------------------------------------------------------------------------
#define MSTRIDE 272
#define CK_BUFA 0
#define CK_BUFB (32 * MSTRIDE)
#define CK_VX   (2 * 32 * MSTRIDE)
#define CK_VA   (CK_VX + 64 * 16)
#define CK_VB   (CK_VA + 32 * 16)
#define CK_SMEM (CK_VB + 32 * 16)

__global__ __launch_bounds__(256) void k_chunk() {
    extern __shared__ float sm[];
    float* bufA = sm + CK_BUFA;
    float* bufB = sm + CK_BUFB;
    float* VX   = sm + CK_VX;
    float* Va   = sm + CK_VA;
    float* Vb   = sm + CK_VB;
    const int tid = threadIdx.x;
    const int bc = blockIdx.x;
    const long rowbase = (long)bc * CHUNK;

#pragma unroll
    for (int it = 0; it < 8; it++) {
        int i4 = it * 256 + tid;
        int m = i4 >> 6, e4 = (i4 & 63) * 4;
        *(float4*)&bufA[m * MSTRIDE + e4] =
            *(const float4*)&g_A[(rowbase + 2 * m) * 256 + e4];
    }
    *(float4*)&VX[tid * 4] = *(const float4*)&g_Bx[rowbase * DS + tid * 4];
    __syncthreads();

#pragma unroll
    for (int rep = 0; rep < 2; rep++) {
        int r = rep * 256 + tid;
        int m = r >> 4, i = r & 15;
        const float* arow = &g_A[(rowbase + 2 * m + 1) * 256 + i * 16];
        float4 a0 = *(const float4*)&arow[0];
        float4 a1 = *(const float4*)&arow[4];
        float4 a2 = *(const float4*)&arow[8];
        float4 a3 = *(const float4*)&arow[12];
        float av[16] = {a0.x, a0.y, a0.z, a0.w, a1.x, a1.y, a1.z, a1.w,
                        a2.x, a2.y, a2.z, a2.w, a3.x, a3.y, a3.z, a3.w};
        float acc[16];
#pragma unroll
        for (int l = 0; l < 16; l++) acc[l] = 0.f;
        float accv = VX[(2 * m + 1) * 16 + i];
#pragma unroll
        for (int q = 0; q < 16; q++) {
            float aq = av[q];
            float4 b0 = *(const float4*)&bufA[m * MSTRIDE + q * 16 + 0];
            float4 b1 = *(const float4*)&bufA[m * MSTRIDE + q * 16 + 4];
            float4 b2 = *(const float4*)&bufA[m * MSTRIDE + q * 16 + 8];
            float4 b3 = *(const float4*)&bufA[m * MSTRIDE + q * 16 + 12];
            acc[0]  += aq * b0.x; acc[1]  += aq * b0.y;
            acc[2]  += aq * b0.z; acc[3]  += aq * b0.w;
            acc[4]  += aq * b1.x; acc[5]  += aq * b1.y;
            acc[6]  += aq * b1.z; acc[7]  += aq * b1.w;
            acc[8]  += aq * b2.x; acc[9]  += aq * b2.y;
            acc[10] += aq * b2.z; acc[11] += aq * b2.w;
            acc[12] += aq * b3.x; acc[13] += aq * b3.y;
            acc[14] += aq * b3.z; acc[15] += aq * b3.w;
            accv += aq * VX[2 * m * 16 + q];
        }
#pragma unroll
        for (int l4 = 0; l4 < 4; l4++)
            *(float4*)&bufB[m * MSTRIDE + i * 16 + l4 * 4] =
                make_float4(acc[l4 * 4], acc[l4 * 4 + 1],
                            acc[l4 * 4 + 2], acc[l4 * 4 + 3]);
        Vb[m * 16 + i] = accv;
    }
    __syncthreads();

    float* src = bufB; float* dst = bufA;
    float* vs = Vb;    float* vd = Va;
#pragma unroll
    for (int lev = 1; lev <= 5; lev++) {
        int nmerge = 32 >> lev;
        int rows = nmerge * 16;
        if (tid < rows) {
            int m = tid >> 4, i = tid & 15;
            const float* a1p = &src[(2 * m + 1) * MSTRIDE + i * 16];
            float4 a0 = *(const float4*)&a1p[0];
            float4 a1 = *(const float4*)&a1p[4];
            float4 a2 = *(const float4*)&a1p[8];
            float4 a3 = *(const float4*)&a1p[12];
            float av[16] = {a0.x, a0.y, a0.z, a0.w, a1.x, a1.y, a1.z, a1.w,
                            a2.x, a2.y, a2.z, a2.w, a3.x, a3.y, a3.z, a3.w};
            float acc[16];
#pragma unroll
            for (int l = 0; l < 16; l++) acc[l] = 0.f;
            float accv = vs[(2 * m + 1) * 16 + i];
#pragma unroll
            for (int q = 0; q < 16; q++) {
                float aq = av[q];
                const float* bp = &src[2 * m * MSTRIDE + q * 16];
                float4 b0 = *(const float4*)&bp[0];
                float4 b1 = *(const float4*)&bp[4];
                float4 b2 = *(const float4*)&bp[8];
                float4 b3 = *(const float4*)&bp[12];
                acc[0]  += aq * b0.x; acc[1]  += aq * b0.y;
                acc[2]  += aq * b0.z; acc[3]  += aq * b0.w;
                acc[4]  += aq * b1.x; acc[5]  += aq * b1.y;
                acc[6]  += aq * b1.z; acc[7]  += aq * b1.w;
                acc[8]  += aq * b2.x; acc[9]  += aq * b2.y;
                acc[10] += aq * b2.z; acc[11] += aq * b2.w;
                acc[12] += aq * b3.x; acc[13] += aq * b3.y;
                acc[14] += aq * b3.z; acc[15] += aq * b3.w;
                accv += aq * vs[2 * m * 16 + q];
            }
#pragma unroll
            for (int l4 = 0; l4 < 4; l4++)
                *(float4*)&dst[m * MSTRIDE + i * 16 + l4 * 4] =
                    make_float4(acc[l4 * 4], acc[l4 * 4 + 1],
                                acc[l4 * 4 + 2], acc[l4 * 4 + 3]);
            vd[m * 16 + i] = accv;
        }
        __syncthreads();
        float* t = src; src = dst; dst = t;
        float* tv = vs; vs = vd; vd = tv;
    }

    g_P[(long)bc * 256 + tid] = src[tid];
    if (tid < 16) g_v[bc * DS + tid] = vs[tid];
}

// ---------------------------------------------------------------------------
// Kernel 1d: superchunk combine. One block per (batch, super): tree over 8
// chunk (P,v) pairs -> (SP, Sv). 3 levels, all in smem.
// ---------------------------------------------------------------------------
#define SST 260
__global__ __launch_bounds__(256) void k_super() {
    __shared__ float P[2][8 * SST];
    __shared__ float V[2][8 * 16];
    const int tid = threadIdx.x;
    const int bs = blockIdx.x;                  // b*NSUPER + s
    const long cbase = (long)bs * SCH;

#pragma unroll
    for (int e = 0; e < 8; e++) {
        int idx = e * 256 + tid;                // 0..2047
        int m = idx >> 8, ij = idx & 255;
        P[0][m * SST + ij] = g_P[(cbase + m) * 256 + ij];
    }
    if (tid < 128) V[0][tid] = g_v[cbase * DS + tid];
    __syncthreads();

    int cur = 0;
#pragma unroll
    for (int lev = 0; lev < 3; lev++) {
        int nm = 4 >> lev;                      // 4, 2, 1 merges
        int elems = nm * 256;
#pragma unroll
        for (int e = 0; e < 4; e++) {
            int idx = e * 256 + tid;
            if (idx < elems) {
                int m = idx >> 8, ij = idx & 255;
                int i = ij >> 4, j = ij & 15;
                const float* P1 = &P[cur][(2 * m + 1) * SST + i * 16];
                const float* P0 = &P[cur][2 * m * SST];
                float s = 0.f;
#pragma unroll
                for (int q = 0; q < 16; q++) s += P1[q] * P0[q * 16 + j];
                P[cur ^ 1][m * SST + ij] = s;
                if (j == 0) {
                    float sv = V[cur][(2 * m + 1) * 16 + i];
                    const float* V0 = &V[cur][2 * m * 16];
#pragma unroll
                    for (int q = 0; q < 16; q++) sv += P1[q] * V0[q];
                    V[cur ^ 1][m * 16 + i] = sv;
                }
            }
        }
        __syncthreads();
        cur ^= 1;
    }

    g_SP[(long)bs * 256 + tid] = P[cur][tid];
    if (tid < 16) g_Sv[bs * DS + tid] = V[cur][tid];
}

// ---------------------------------------------------------------------------
// Kernel 2: sequential scan over 8 superchunks per batch (depth 8).
// ---------------------------------------------------------------------------
__global__ __launch_bounds__(32) void k_scan2() {
    const int b = blockIdx.x;
    const int lane = threadIdx.x;
    const long base = (long)b * NSUPER;

    float h[16];
#pragma unroll
    for (int q = 0; q < 16; q++) h[q] = 0.f;
    float mine = 0.f;

    float4 p0 = {0,0,0,0}, p1 = p0, p2 = p0, p3 = p0;
    float v = 0.f;
    if (lane < 16) {
        const float* P = &g_SP[base * 256 + lane * 16];
        p0 = *(const float4*)&P[0];
        p1 = *(const float4*)&P[4];
        p2 = *(const float4*)&P[8];
        p3 = *(const float4*)&P[12];
        v = g_Sv[base * DS + lane];
    }

    for (int s = 0; s < NSUPER; s++) {
        float4 q0 = p0, q1 = p1, q2 = p2, q3 = p3;
        float vn = v;
        if (lane < 16 && s + 1 < NSUPER) {
            const float* Pn = &g_SP[(base + s + 1) * 256 + lane * 16];
            q0 = *(const float4*)&Pn[0];
            q1 = *(const float4*)&Pn[4];
            q2 = *(const float4*)&Pn[8];
            q3 = *(const float4*)&Pn[12];
            vn = g_Sv[(base + s + 1) * DS + lane];
        }
        float hn = 0.f;
        if (lane < 16) {
            g_sh0[(base + s) * DS + lane] = mine;
            float s0 = v + p0.x * h[0] + p0.y * h[1] + p0.z * h[2] + p0.w * h[3];
            float s1 = p1.x * h[4] + p1.y * h[5] + p1.z * h[6] + p1.w * h[7];
            float s2 = p2.x * h[8] + p2.y * h[9] + p2.z * h[10] + p2.w * h[11];
            float s3 = p3.x * h[12] + p3.y * h[13] + p3.z * h[14] + p3.w * h[15];
            hn = (s0 + s1) + (s2 + s3);
            mine = hn;
        }
#pragma unroll
        for (int q = 0; q < 16; q++)
            h[q] = __shfl_sync(0xffffffffu, hn, q);
        p0 = q0; p1 = q1; p2 = q2; p3 = q3; v = vn;
    }
}

// ---------------------------------------------------------------------------
// Kernel 2b: within-superchunk chunk-level scan (8 steps), parallel across
// the 64 (batch, super) pairs. Produces g_h0 for every chunk.
// ---------------------------------------------------------------------------
__global__ __launch_bounds__(32) void k_mid() {
    const int bs = blockIdx.x;                  // b*NSUPER + s
    const int lane = threadIdx.x;
    const long cbase = (long)bs * SCH;

    float hv = (lane < 16) ? g_sh0[bs * DS + lane] : 0.f;
    float h[16];
#pragma unroll
    for (int q = 0; q < 16; q++) h[q] = __shfl_sync(0xffffffffu, hv, q);
    float mine = hv;

    float4 p0 = {0,0,0,0}, p1 = p0, p2 = p0, p3 = p0;
    float v = 0.f;
    if (lane < 16) {
        const float* P = &g_P[cbase * 256 + lane * 16];
        p0 = *(const float4*)&P[0];
        p1 = *(const float4*)&P[4];
        p2 = *(const float4*)&P[8];
        p3 = *(const float4*)&P[12];
        v = g_v[cbase * DS + lane];
    }

    for (int c = 0; c < SCH; c++) {
        float4 q0 = p0, q1 = p1, q2 = p2, q3 = p3;
        float vn = v;
        if (lane < 16 && c + 1 < SCH) {
            const float* Pn = &g_P[(cbase + c + 1) * 256 + lane * 16];
            q0 = *(const float4*)&Pn[0];
            q1 = *(const float4*)&Pn[4];
            q2 = *(const float4*)&Pn[8];
            q3 = *(const float4*)&Pn[12];
            vn = g_v[(cbase + c + 1) * DS + lane];
        }
        float hn = 0.f;
        if (lane < 16) {
            g_h0[(cbase + c) * DS + lane] = mine;
            float s0 = v + p0.x * h[0] + p0.y * h[1] + p0.z * h[2] + p0.w * h[3];
            float s1 = p1.x * h[4] + p1.y * h[5] + p1.z * h[6] + p1.w * h[7];
            float s2 = p2.x * h[8] + p2.y * h[9] + p2.z * h[10] + p2.w * h[11];
            float s3 = p3.x * h[12] + p3.y * h[13] + p3.z * h[14] + p3.w * h[15];
            hn = (s0 + s1) + (s2 + s3);
            mine = hn;
        }
#pragma unroll
        for (int q = 0; q < 16; q++)
            h[q] = __shfl_sync(0xffffffffu, hn, q);
        p0 = q0; p1 = q1; p2 = q2; p3 = q3; v = vn;
    }
}

// ---------------------------------------------------------------------------
// Kernel 2c: per-chunk replay -> g_H
// ---------------------------------------------------------------------------
__global__ __launch_bounds__(32) void k_replay() {
    const int bc = blockIdx.x;
    const int lane = threadIdx.x;
    const long rowbase = (long)bc * CHUNK;

    float h[16];
#pragma unroll
    for (int q = 0; q < 16; q++) h[q] = g_h0[bc * DS + q];

    float4 a0 = {0,0,0,0}, a1 = a0, a2 = a0, a3 = a0;
    float bx = 0.f;
    if (lane < 16) {
        const float* Arow = &g_A[rowbase * 256 + lane * 16];
        a0 = *(const float4*)&Arow[0];
        a1 = *(const float4*)&Arow[4];
        a2 = *(const float4*)&Arow[8];
        a3 = *(const float4*)&Arow[12];
        bx = g_Bx[rowbase * DS + lane];
    }
    for (int t = 0; t < CHUNK; t++) {
        float4 n0 = a0, n1 = a1, n2 = a2, n3 = a3;
        float bxn = bx;
        if (lane < 16 && t + 1 < CHUNK) {
            const float* An = &g_A[(rowbase + t + 1) * 256 + lane * 16];
            n0 = *(const float4*)&An[0];
            n1 = *(const float4*)&An[4];
            n2 = *(const float4*)&An[8];
            n3 = *(const float4*)&An[12];
            bxn = g_Bx[(rowbase + t + 1) * DS + lane];
        }
        float hn = 0.f;
        if (lane < 16) {
            float s0 = bx + a0.x * h[0] + a0.y * h[1] + a0.z * h[2] + a0.w * h[3];
            float s1 = a1.x * h[4] + a1.y * h[5] + a1.z * h[6] + a1.w * h[7];
            float s2 = a2.x * h[8] + a2.y * h[9] + a2.z * h[10] + a2.w * h[11];
            float s3 = a3.x * h[12] + a3.y * h[13] + a3.z * h[14] + a3.w * h[15];
            hn = (s0 + s1) + (s2 + s3);
            g_H[(rowbase + t) * DS + lane] = hn;
        }
#pragma unroll
        for (int q = 0; q < 16; q++)
            h[q] = __shfl_sync(0xffffffffu, hn, q);
        a0 = n0; a1 = n1; a2 = n2; a3 = n3; bx = bxn;
    }
}

// ---------------------------------------------------------------------------
// Kernel 3 (tensor): out[m,d] = sum_n h[m,n] * (x @ W_C[:,n,:])[m,d] + h @ b_C'
// ---------------------------------------------------------------------------
#define KC_WS   (128 * 68)
#define KC_HS   (KC_WS + 64 * 68)
#define KC_SMEM (KC_HS + 128 * 17)

__global__ __launch_bounds__(256) void k_outC(const float* __restrict__ x,
                                              const float* __restrict__ W_C,
                                              const float* __restrict__ b_C,
                                              float* __restrict__ out) {
    extern __shared__ float sm[];
    float* Xs = sm;             // [128][68] tf32 x
    float* Ws = sm + KC_WS;     // [64][68]  tf32 W_C slice (reused for b_C)
    float* Hs = sm + KC_HS;     // [128][17] fp32 h
    const int tid = threadIdx.x;
    const int m0 = blockIdx.x * 128;

#pragma unroll
    for (int it = 0; it < 8; it++) {
        int i4 = it * 256 + tid;
        int row = i4 >> 4, c4 = (i4 & 15) * 4;
        float4 v = *(const float4*)&x[(long)(m0 + row) * 64 + c4];
        Xs[row * 68 + c4 + 0] = f2tf(v.x);
        Xs[row * 68 + c4 + 1] = f2tf(v.y);
        Xs[row * 68 + c4 + 2] = f2tf(v.z);
        Xs[row * 68 + c4 + 3] = f2tf(v.w);
    }
#pragma unroll
    for (int it = 0; it < 2; it++) {
        int i4 = it * 256 + tid;
        int row = i4 >> 2, c4 = (i4 & 3) * 4;
        float4 v = *(const float4*)&g_H[(long)(m0 + row) * DS + c4];
        Hs[row * 17 + c4 + 0] = v.x;
        Hs[row * 17 + c4 + 1] = v.y;
        Hs[row * 17 + c4 + 2] = v.z;
        Hs[row * 17 + c4 + 3] = v.w;
    }

    int wk[4], wd[4];
#pragma unroll
    for (int it = 0; it < 4; it++) {
        int i4 = it * 256 + tid;
        wk[it] = i4 >> 4;
        wd[it] = (i4 & 15) * 4;
    }
    float4 wreg[4];
#pragma unroll
    for (int it = 0; it < 4; it++)
        wreg[it] = *(const float4*)&W_C[(long)wk[it] * 1024 + wd[it]];   // n=0

    const int wid = tid >> 5, lane = tid & 31;
    const int g = lane >> 2, tig = lane & 3;
    const int wm = wid & 3, wn = wid >> 2;
    const int mbase = wm * 32, nbase = wn * 32;

    float oacc[2][4][4];
#pragma unroll
    for (int mt = 0; mt < 2; mt++)
#pragma unroll
        for (int nt = 0; nt < 4; nt++)
#pragma unroll
            for (int j = 0; j < 4; j++) oacc[mt][nt][j] = 0.f;

    for (int n = 0; n < 16; n++) {
        __syncthreads();
#pragma unroll
        for (int it = 0; it < 4; it++) {
            Ws[wk[it] * 68 + wd[it] + 0] = f2tf(wreg[it].x);
            Ws[wk[it] * 68 + wd[it] + 1] = f2tf(wreg[it].y);
            Ws[wk[it] * 68 + wd[it] + 2] = f2tf(wreg[it].z);
            Ws[wk[it] * 68 + wd[it] + 3] = f2tf(wreg[it].w);
        }
        __syncthreads();
        if (n + 1 < 16) {
#pragma unroll
            for (int it = 0; it < 4; it++)
                wreg[it] = *(const float4*)
                    &W_C[(long)wk[it] * 1024 + (n + 1) * 64 + wd[it]];
        }

        float c[2][4][4];
#pragma unroll
        for (int mt = 0; mt < 2; mt++)
#pragma unroll
            for (int nt = 0; nt < 4; nt++)
#pragma unroll
                for (int j = 0; j < 4; j++) c[mt][nt][j] = 0.f;

#pragma unroll
        for (int ks = 0; ks < 8; ks++) {
            const int k0 = ks * 8;
            unsigned a[2][4];
#pragma unroll
            for (int mt = 0; mt < 2; mt++) {
                int r = mbase + mt * 16 + g;
                a[mt][0] = fu(Xs[r * 68 + k0 + tig]);
                a[mt][1] = fu(Xs[(r + 8) * 68 + k0 + tig]);
                a[mt][2] = fu(Xs[r * 68 + k0 + tig + 4]);
                a[mt][3] = fu(Xs[(r + 8) * 68 + k0 + tig + 4]);
            }
            unsigned b[4][2];
#pragma unroll
            for (int nt = 0; nt < 4; nt++) {
                int nn = nbase + nt * 8 + g;
                b[nt][0] = fu(Ws[(k0 + tig) * 68 + nn]);
                b[nt][1] = fu(Ws[(k0 + tig + 4) * 68 + nn]);
            }
#pragma unroll
            for (int mt = 0; mt < 2; mt++)
#pragma unroll
                for (int nt = 0; nt < 4; nt++)
                    mma8(c[mt][nt], a[mt][0], a[mt][1], a[mt][2], a[mt][3],
                         b[nt][0], b[nt][1]);
        }

#pragma unroll
        for (int mt = 0; mt < 2; mt++) {
            int r0 = mbase + mt * 16 + g;
            float ha = Hs[r0 * 17 + n];
            float hb = Hs[(r0 + 8) * 17 + n];
#pragma unroll
            for (int nt = 0; nt < 4; nt++) {
                oacc[mt][nt][0] += ha * c[mt][nt][0];
                oacc[mt][nt][1] += ha * c[mt][nt][1];
                oacc[mt][nt][2] += hb * c[mt][nt][2];
                oacc[mt][nt][3] += hb * c[mt][nt][3];
            }
        }
    }

    __syncthreads();
    {
        int nn = tid >> 4, c4 = (tid & 15) * 4;
        float4 v = *(const float4*)&b_C[nn * 64 + c4];
        Ws[nn * 68 + c4 + 0] = v.x;
        Ws[nn * 68 + c4 + 1] = v.y;
        Ws[nn * 68 + c4 + 2] = v.z;
        Ws[nn * 68 + c4 + 3] = v.w;
    }
    __syncthreads();

#pragma unroll
    for (int mt = 0; mt < 2; mt++) {
        int r0 = mbase + mt * 16 + g;
        int r1 = r0 + 8;
#pragma unroll
        for (int nt = 0; nt < 4; nt++) {
            int col = nbase + nt * 8 + tig * 2;
            float s00 = 0.f, s01 = 0.f, s10 = 0.f, s11 = 0.f;
#pragma unroll
            for (int nn = 0; nn < 16; nn++) {
                float ha = Hs[r0 * 17 + nn], hb = Hs[r1 * 17 + nn];
                float w0 = Ws[nn * 68 + col], w1 = Ws[nn * 68 + col + 1];
                s00 += ha * w0; s01 += ha * w1;
                s10 += hb * w0; s11 += hb * w1;
            }
            *(float2*)&out[(long)(m0 + r0) * 64 + col] =
                make_float2(oacc[mt][nt][0] + s00, oacc[mt][nt][1] + s01);
            *(float2*)&out[(long)(m0 + r1) * 64 + col] =
                make_float2(oacc[mt][nt][2] + s10, oacc[mt][nt][3] + s11);
        }
    }
}

// ---------------------------------------------------------------------------
extern "C" void kernel_launch(void* const* d_in, const int* in_sizes, int n_in,
                              void* d_out, int out_size) {
    const float* x   = (const float*)d_in[0];
    const float* W_A = (const float*)d_in[1];
    const float* b_A = (const float*)d_in[2];
    const float* W_B = (const float*)d_in[3];
    const float* b_B = (const float*)d_in[4];
    const float* W_C = (const float*)d_in[5];
    const float* b_C = (const float*)d_in[6];
    float* out = (float*)d_out;

    const int smA = (128 * 68 + 64 * 68) * sizeof(float);
    const int smB = (128 * 68 + 64 * 132 + 128 * 4) * sizeof(float);
    const int smC = CK_SMEM * sizeof(float);
    const int smO = KC_SMEM * sizeof(float);
    cudaFuncSetAttribute(k_projA, cudaFuncAttributeMaxDynamicSharedMemorySize, smA);
    cudaFuncSetAttribute(k_projB, cudaFuncAttributeMaxDynamicSharedMemorySize, smB);
    cudaFuncSetAttribute(k_chunk, cudaFuncAttributeMaxDynamicSharedMemorySize, smC);
    cudaFuncSetAttribute(k_outC,  cudaFuncAttributeMaxDynamicSharedMemorySize, smO);

    k_projA<<<dim3(ROWS / 128, 4), 256, smA>>>(x, W_A, b_A);
    k_projB<<<dim3(ROWS / 128, 8), 256, smB>>>(x, W_B, b_B);
    k_chunk<<<BATCH * NCHUNK, 256, smC>>>();
    k_super<<<BATCH * NSUPER, 256>>>();
    k_scan2<<<BATCH, 32>>>();
    k_mid<<<BATCH * NSUPER, 32>>>();
    k_replay<<<BATCH * NCHUNK, 32>>>();
    k_outC<<<ROWS / 128, 256, smO>>>(x, W_C, b_C, out);
}